// round 8
// baseline (speedup 1.0000x reference)
#include <cuda_runtime.h>
#include <math.h>

#define B_PTS 16384
#define ENC   63
#define LAT   256
#define NE    8
#define HID   256
#define NOUT  4
#define CHUNK 32
#define EIN   95      // ENC + CHUNK
#define GIN   319     // ENC + LAT
#define BM    64      // points per CTA tile
#define PCH   68      // smem pitch (floats) for k-major activation storage
#define KT    4       // k-tile depth for weight staging
#define EPS_F 2.2204460492503131e-16f

// ---------------- scratch (no allocations allowed) ----------------
__device__ int   d_counts[NE];
__device__ int   d_bucket[NE * B_PTS];
__device__ float d_gateval[B_PTS];

__global__ void zero_counts_kernel() {
    if (threadIdx.x < NE) d_counts[threadIdx.x] = 0;
}

// ---------------- GEMM building blocks ----------------
// CTA tile: 64 points x 256 cols, 256 threads, 8x8 micro-tile per thread.
// Activations live in SMEM k-major: src[k*PCH + p]. Weights streamed from
// global (row stride 256) through a double-buffered KTx256 SMEM tile.

__device__ __forceinline__ void zero_acc(float acc[8][8]) {
#pragma unroll
    for (int i = 0; i < 8; i++)
#pragma unroll
        for (int j = 0; j < 8; j++) acc[i][j] = 0.0f;
}

__device__ __forceinline__ void ldg_w(float4& v,
                                      const float* __restrict__ Wg,
                                      int k0, int kReal, int tid) {
    int r = tid >> 6;            // 0..3  (row within k-tile)
    int c = (tid & 63) << 2;     // 0..252 (4 floats per thread)
    int k = k0 + r;
    if (k < kReal) {
        v = *reinterpret_cast<const float4*>(Wg + (size_t)k * 256 + c);
    } else {
        v = make_float4(0.f, 0.f, 0.f, 0.f);
    }
}

__device__ __forceinline__ void sts_w(float* buf, float4 v, int tid) {
    int r = tid >> 6;
    int c = (tid & 63) << 2;
    *reinterpret_cast<float4*>(buf + r * 256 + c) = v;
}

// acc += src_s[0:kTiles*KT, 0:64]^T * W[0:kReal, 0:256]
// (padded src rows beyond real K must be zeroed by the caller; padded W rows load 0)
__device__ __forceinline__ void gemm_phase(float acc[8][8],
                                           const float* __restrict__ src_s, int kTiles,
                                           const float* __restrict__ Wg, int kReal,
                                           float* Ws, int tid, int tx, int ty) {
    __syncthreads();  // protect Ws buffers from any preceding phase's readers
    float4 pf;
    ldg_w(pf, Wg, 0, kReal, tid);
    for (int kt = 0; kt < kTiles; kt++) {
        float* buf = Ws + (kt & 1) * (KT * 256);
        sts_w(buf, pf, tid);
        if (kt + 1 < kTiles) ldg_w(pf, Wg, (kt + 1) * KT, kReal, tid);
        __syncthreads();
        const float* srck = src_s + kt * (KT * PCH);
#pragma unroll
        for (int k = 0; k < KT; k++) {
            float4 a0 = *reinterpret_cast<const float4*>(srck + k * PCH + ty * 8);
            float4 a1 = *reinterpret_cast<const float4*>(srck + k * PCH + ty * 8 + 4);
            float4 w0 = *reinterpret_cast<const float4*>(buf + k * 256 + tx * 4);
            float4 w1 = *reinterpret_cast<const float4*>(buf + k * 256 + tx * 4 + 128);
            float a[8] = {a0.x, a0.y, a0.z, a0.w, a1.x, a1.y, a1.z, a1.w};
            float w[8] = {w0.x, w0.y, w0.z, w0.w, w1.x, w1.y, w1.z, w1.w};
#pragma unroll
            for (int i = 0; i < 8; i++)
#pragma unroll
                for (int j = 0; j < 8; j++)
                    acc[i][j] = fmaf(a[i], w[j], acc[i][j]);
        }
        // no trailing sync needed: next iter writes the other buffer, and its
        // mid-iteration sync orders reuse two tiles later.
    }
}

// Write acc (+bias, optional relu) into dst k-major. Caller must sync before
// (all readers of dst done) and after (before anyone reads dst).
__device__ __forceinline__ void store_act(const float acc[8][8], float* dst,
                                          const float* bias_s, bool relu,
                                          int tx, int ty) {
#pragma unroll
    for (int j = 0; j < 8; j++) {
        int c = (j < 4) ? (tx * 4 + j) : (128 + tx * 4 + (j - 4));
        float b = bias_s[c];
#pragma unroll
        for (int i = 0; i < 8; i++) {
            float v = acc[i][j] + b;
            if (relu) v = fmaxf(v, 0.0f);
            dst[c * PCH + ty * 8 + i] = v;
        }
    }
}

// one full 256->256 relu layer (weights at Wg, bias at Bg), act_s in place
__device__ __forceinline__ void dense_layer_256(float acc[8][8], float* act_s,
                                                const float* __restrict__ Wg,
                                                const float* __restrict__ Bg,
                                                float* Ws, float* bias_s,
                                                int tid, int tx, int ty) {
    bias_s[tid] = Bg[tid];
    zero_acc(acc);
    gemm_phase(acc, act_s, 64, Wg, 256, Ws, tid, tx, ty);
    __syncthreads();
    store_act(acc, act_s, bias_s, true, tx, ty);
    __syncthreads();
}

// ---------------- gate kernel: 3 layers + LN + softmax + routing ----------------
// act_s ALIASES in_s: the 320-row input buffer is dead after layer 1's GEMM
// (all reads complete before the barrier preceding store_act).
__global__ __launch_bounds__(256, 2)
void gate_kernel(const float* __restrict__ x, const float* __restrict__ lat,
                 const float* __restrict__ gw1, const float* __restrict__ gb1,
                 const float* __restrict__ gw2, const float* __restrict__ gb2,
                 const float* __restrict__ lng, const float* __restrict__ lnb,
                 const float* __restrict__ gw3, const float* __restrict__ gb3) {
    extern __shared__ float sm[];
    float* in_s   = sm;                     // 320*PCH (row 319 zero pad)
    float* act_s  = in_s;                   // alias: reuses rows 0..255 after L1
    float* Ws     = in_s + 320 * PCH;       // 2*KT*256 (also layer-3 partial scratch)
    float* bias_s = Ws + 2 * KT * 256;      // 256
    float* w3_s   = bias_s + 256;           // 256*8
    float* mu_s   = w3_s + 2048;            // 64
    float* rs_s   = mu_s + 64;              // 64
    float* part_s = rs_s + 64;              // 4*64 partial sums

    int tid = threadIdx.x;
    int tx = tid & 31, ty = tid >> 5;
    int p0 = blockIdx.x * BM;

    // stage g_in = concat(x, shape_latent) transposed (k-major)
    for (int idx = tid; idx < 320 * BM; idx += 256) {
        int p = idx / 320;
        int k = idx - p * 320;
        int gp = p0 + p;
        float v;
        if (k < ENC)       v = x[(size_t)gp * ENC + k];
        else if (k < GIN)  v = lat[(size_t)gp * LAT + (k - ENC)];
        else               v = 0.0f;
        in_s[k * PCH + p] = v;
    }
    bias_s[tid] = gb1[tid];

    float acc[8][8];

    // layer 1: [319]->256, relu
    zero_acc(acc);
    gemm_phase(acc, in_s, 80, gw1, GIN, Ws, tid, tx, ty);
    __syncthreads();                 // all reads of in_s done -> safe to overwrite
    store_act(acc, act_s, bias_s, true, tx, ty);
    __syncthreads();

    // layer 2: 256->256, no relu
    bias_s[tid] = gb2[tid];
    zero_acc(acc);
    gemm_phase(acc, act_s, 64, gw2, 256, Ws, tid, tx, ty);
    __syncthreads();
    store_act(acc, act_s, bias_s, false, tx, ty);
    __syncthreads();

    // LayerNorm (two-pass, biased variance, eps 1e-5) — parallel reduction:
    // 256 threads compute 64-k partials (seg = tid>>6, p = tid&63), 64 combine.
    {
        int p = tid & 63, seg = tid >> 6;
        float s = 0.0f;
        for (int k = seg * 64; k < seg * 64 + 64; k++) s += act_s[k * PCH + p];
        part_s[seg * 64 + p] = s;
    }
    __syncthreads();
    if (tid < BM) {
        int p = tid;
        mu_s[p] = (part_s[p] + part_s[64 + p] + part_s[128 + p] + part_s[192 + p])
                  * (1.0f / 256.0f);
    }
    __syncthreads();
    {
        int p = tid & 63, seg = tid >> 6;
        float mu = mu_s[p];
        float v2 = 0.0f;
        for (int k = seg * 64; k < seg * 64 + 64; k++) {
            float d = act_s[k * PCH + p] - mu;
            v2 += d * d;
        }
        part_s[seg * 64 + p] = v2;
    }
    for (int idx = tid; idx < 2048; idx += 256) w3_s[idx] = gw3[idx];
    __syncthreads();
    if (tid < BM) {
        int p = tid;
        float v2 = part_s[p] + part_s[64 + p] + part_s[128 + p] + part_s[192 + p];
        rs_s[p] = rsqrtf(v2 * (1.0f / 256.0f) + 1e-5f);
    }
    __syncthreads();
    for (int idx = tid; idx < 256 * BM; idx += 256) {
        int k = idx >> 6, p = idx & 63;
        float v = act_s[k * PCH + p];
        act_s[k * PCH + p] = (v - mu_s[p]) * rs_s[p] * lng[k] + lnb[k];
    }
    __syncthreads();

    // layer 3: 256->8, parallel over 4 k-segments (partials in Ws — free here,
    // last gemm readers barriered off long before).
    {
        int p = tid & 63, seg = tid >> 6;
        float l[NE];
#pragma unroll
        for (int e = 0; e < NE; e++) l[e] = 0.0f;
        for (int k = seg * 64; k < seg * 64 + 64; k++) {
            float a = act_s[k * PCH + p];
#pragma unroll
            for (int e = 0; e < NE; e++) l[e] = fmaf(a, w3_s[k * 8 + e], l[e]);
        }
        float4* dst = reinterpret_cast<float4*>(Ws + seg * 512 + p * 8);
        dst[0] = make_float4(l[0], l[1], l[2], l[3]);
        dst[1] = make_float4(l[4], l[5], l[6], l[7]);
    }
    __syncthreads();

    // combine partials, softmax, argmax, routing (64 threads)
    if (tid < BM) {
        int p = tid;
        float l[NE];
#pragma unroll
        for (int e = 0; e < NE; e++) l[e] = gb3[e];
#pragma unroll
        for (int seg = 0; seg < 4; seg++) {
            const float4* src = reinterpret_cast<const float4*>(Ws + seg * 512 + p * 8);
            float4 a0 = src[0], a1 = src[1];
            l[0] += a0.x; l[1] += a0.y; l[2] += a0.z; l[3] += a0.w;
            l[4] += a1.x; l[5] += a1.y; l[6] += a1.z; l[7] += a1.w;
        }
        float m = l[0];
#pragma unroll
        for (int e = 1; e < NE; e++) m = fmaxf(m, l[e]);
        float g[NE], ssum = 0.0f;
#pragma unroll
        for (int e = 0; e < NE; e++) { g[e] = expf(l[e] - m); ssum += g[e]; }
        float inv = 1.0f / ssum;
#pragma unroll
        for (int e = 0; e < NE; e++) g[e] *= inv;
        // first-occurrence argmax over post-softmax gates (mirrors jnp.argmax)
        int bi = 0; float best = g[0];
#pragma unroll
        for (int e = 1; e < NE; e++) if (g[e] > best) { best = g[e]; bi = e; }
        int gp = p0 + p;
        d_gateval[gp] = best;
        int pos = atomicAdd(&d_counts[bi], 1);
        d_bucket[bi * B_PTS + pos] = gp;
    }
}

// ---------------- expert kernel: 7-layer NeRF MLP with skip at layer 5 ----------------
__global__ __launch_bounds__(256, 2)
void expert_kernel(const float* __restrict__ x, const float* __restrict__ lat,
                   const float* __restrict__ ew0, const float* __restrict__ eb0,
                   const float* __restrict__ ew1, const float* __restrict__ eb1,
                   const float* __restrict__ ew2, const float* __restrict__ eb2,
                   const float* __restrict__ ew3, const float* __restrict__ eb3,
                   const float* __restrict__ ew4, const float* __restrict__ eb4,
                   const float* __restrict__ ew5, const float* __restrict__ eb5,
                   const float* __restrict__ ew6, const float* __restrict__ eb6,
                   const float* __restrict__ ewo, const float* __restrict__ ebo,
                   float* __restrict__ out) {
    extern __shared__ float sm[];
    float* h0_s   = sm;                     // 96*PCH (row 95 zero pad)
    float* act_s  = h0_s + 96 * PCH;        // 256*PCH
    float* Ws     = act_s + 256 * PCH;      // 2*KT*256 (also head partial scratch)
    float* bias_s = Ws + 2 * KT * 256;      // 256
    float* wo_s   = bias_s + 256;           // 256*4
    int*   idx_s  = (int*)(wo_s + 1024);    // 64

    int e = blockIdx.y;
    int cnt = d_counts[e];
    int base = blockIdx.x * BM;
    if (base >= cnt) return;
    int nv = min(BM, cnt - base);

    int tid = threadIdx.x;
    int tx = tid & 31, ty = tid >> 5;

    if (tid < BM) {
        int slot = (tid < nv) ? tid : 0;   // clamp padding to a valid point
        idx_s[tid] = d_bucket[e * B_PTS + base + slot];
    }
    __syncthreads();

    // stage h0 = concat(x, latent chunk e) transposed (k-major)
    for (int idx = tid; idx < 96 * BM; idx += 256) {
        int k = idx >> 6, p = idx & 63;
        int gp = idx_s[p];
        float v;
        if (k < ENC)      v = x[(size_t)gp * ENC + k];
        else if (k < EIN) v = lat[(size_t)gp * LAT + e * CHUNK + (k - ENC)];
        else              v = 0.0f;
        h0_s[k * PCH + p] = v;
    }
    bias_s[tid] = eb0[e * 256 + tid];

    float acc[8][8];

    // layer 0: [95]->256, relu
    zero_acc(acc);
    gemm_phase(acc, h0_s, 24, ew0 + (size_t)e * EIN * 256, EIN, Ws, tid, tx, ty);
    __syncthreads();
    store_act(acc, act_s, bias_s, true, tx, ty);
    __syncthreads();

    // layers 1-4: 256->256, relu (fully unrolled: compile-time W/B pointers,
    // no local-memory pointer arrays)
    dense_layer_256(acc, act_s, ew1 + (size_t)e * 65536, eb1 + e * 256,
                    Ws, bias_s, tid, tx, ty);
    dense_layer_256(acc, act_s, ew2 + (size_t)e * 65536, eb2 + e * 256,
                    Ws, bias_s, tid, tx, ty);
    dense_layer_256(acc, act_s, ew3 + (size_t)e * 65536, eb3 + e * 256,
                    Ws, bias_s, tid, tx, ty);
    dense_layer_256(acc, act_s, ew4 + (size_t)e * 65536, eb4 + e * 256,
                    Ws, bias_s, tid, tx, ty);

    // layer 5 (skip): [act(256) ; h0(95)] -> 256, relu
    bias_s[tid] = eb5[e * 256 + tid];
    zero_acc(acc);
    gemm_phase(acc, act_s, 64, ew5 + (size_t)e * 351 * 256, 256, Ws, tid, tx, ty);
    gemm_phase(acc, h0_s, 24, ew5 + (size_t)e * 351 * 256 + 256 * 256, EIN, Ws, tid, tx, ty);
    __syncthreads();
    store_act(acc, act_s, bias_s, true, tx, ty);
    __syncthreads();

    // layer 6: 256->256, relu
    bias_s[tid] = eb6[e * 256 + tid];
    zero_acc(acc);
    gemm_phase(acc, act_s, 64, ew6 + (size_t)e * 65536, 256, Ws, tid, tx, ty);
    __syncthreads();
    store_act(acc, act_s, bias_s, true, tx, ty);

    // output head: 256->4, parallel over 4 k-segments (partials in Ws)
    for (int idx = tid; idx < 1024; idx += 256) wo_s[idx] = ewo[(size_t)e * 1024 + idx];
    __syncthreads();   // orders store_act writes + wo_s loads + frees Ws

    {
        int p = tid & 63, seg = tid >> 6;
        float o[NOUT] = {0.f, 0.f, 0.f, 0.f};
        for (int k = seg * 64; k < seg * 64 + 64; k++) {
            float a = act_s[k * PCH + p];
#pragma unroll
            for (int j = 0; j < NOUT; j++) o[j] = fmaf(a, wo_s[k * 4 + j], o[j]);
        }
        *reinterpret_cast<float4*>(Ws + seg * 256 + p * 4) =
            make_float4(o[0], o[1], o[2], o[3]);
    }
    __syncthreads();

    if (tid < nv) {
        int p = tid;
        float o[NOUT];
        float4 a0 = *reinterpret_cast<const float4*>(Ws + p * 4);
        float4 a1 = *reinterpret_cast<const float4*>(Ws + 256 + p * 4);
        float4 a2 = *reinterpret_cast<const float4*>(Ws + 512 + p * 4);
        float4 a3 = *reinterpret_cast<const float4*>(Ws + 768 + p * 4);
        o[0] = a0.x + a1.x + a2.x + a3.x;
        o[1] = a0.y + a1.y + a2.y + a3.y;
        o[2] = a0.z + a1.z + a2.z + a3.z;
        o[3] = a0.w + a1.w + a2.w + a3.w;
        int gp = idx_s[p];
        float gv = d_gateval[gp];
        float r[NOUT];
#pragma unroll
        for (int j = 0; j < NOUT; j++) {
            float y = o[j] + ebo[e * 4 + j];
            float c = gv * expf(y);
            if (c == 0.0f) c = EPS_F;
            r[j] = logf(c);
        }
        *reinterpret_cast<float4*>(out + (size_t)gp * 4) =
            make_float4(r[0], r[1], r[2], r[3]);
    }
}

// ---------------- launch ----------------
extern "C" void kernel_launch(void* const* d_in, const int* in_sizes, int n_in,
                              void* d_out, int out_size) {
    const float* x   = (const float*)d_in[0];
    const float* lat = (const float*)d_in[1];
    const float* gw1 = (const float*)d_in[2];
    const float* gb1 = (const float*)d_in[3];
    const float* gw2 = (const float*)d_in[4];
    const float* gb2 = (const float*)d_in[5];
    const float* lng = (const float*)d_in[6];
    const float* lnb = (const float*)d_in[7];
    const float* gw3 = (const float*)d_in[8];
    const float* gb3 = (const float*)d_in[9];
    const float* ew0 = (const float*)d_in[10];
    const float* eb0 = (const float*)d_in[11];
    const float* ew1 = (const float*)d_in[12];
    const float* eb1 = (const float*)d_in[13];
    const float* ew2 = (const float*)d_in[14];
    const float* eb2 = (const float*)d_in[15];
    const float* ew3 = (const float*)d_in[16];
    const float* eb3 = (const float*)d_in[17];
    const float* ew4 = (const float*)d_in[18];
    const float* eb4 = (const float*)d_in[19];
    const float* ew5 = (const float*)d_in[20];
    const float* eb5 = (const float*)d_in[21];
    const float* ew6 = (const float*)d_in[22];
    const float* eb6 = (const float*)d_in[23];
    const float* ewo = (const float*)d_in[24];
    const float* ebo = (const float*)d_in[25];
    float* out = (float*)d_out;

    const size_t gate_smem = (320 * PCH + 2 * KT * 256 + 256 + 2048 + 128 + 256)
                             * sizeof(float);
    const size_t exp_smem  = (96 * PCH + 256 * PCH + 2 * KT * 256 + 256 + 1024)
                             * sizeof(float) + 64 * sizeof(int);

    cudaFuncSetAttribute(gate_kernel,  cudaFuncAttributeMaxDynamicSharedMemorySize,
                         (int)gate_smem);
    cudaFuncSetAttribute(expert_kernel, cudaFuncAttributeMaxDynamicSharedMemorySize,
                         (int)exp_smem);

    zero_counts_kernel<<<1, 32>>>();
    gate_kernel<<<B_PTS / BM, 256, gate_smem>>>(x, lat, gw1, gb1, gw2, gb2,
                                                lng, lnb, gw3, gb3);
    dim3 eg(B_PTS / BM, NE);
    expert_kernel<<<eg, 256, exp_smem>>>(x, lat, ew0, eb0, ew1, eb1, ew2, eb2,
                                         ew3, eb3, ew4, eb4, ew5, eb5, ew6, eb6,
                                         ewo, ebo, out);
}

// round 9
// speedup vs baseline: 1.0018x; 1.0018x over previous
#include <cuda_runtime.h>
#include <math.h>

#define B_PTS 16384
#define ENC   63
#define LAT   256
#define NE    8
#define HID   256
#define NOUT  4
#define CHUNK 32
#define EIN   95      // ENC + CHUNK
#define GIN   319     // ENC + LAT
#define BM    64      // points per CTA tile
#define PCH   68      // smem pitch (floats) for k-major activation storage
#define KT    4       // k-tile depth for weight staging
#define EPS_F 2.2204460492503131e-16f

// ---------------- scratch (no allocations allowed) ----------------
__device__ int   d_counts[NE];
__device__ int   d_bucket[NE * B_PTS];
__device__ float d_gateval[B_PTS];

__global__ void zero_counts_kernel() {
    if (threadIdx.x < NE) d_counts[threadIdx.x] = 0;
}

// ---------------- GEMM building blocks ----------------
// CTA tile: 64 points x 256 cols, 256 threads, 8x8 micro-tile per thread.
// Activations live in SMEM k-major: src[k*PCH + p]. Weights streamed from
// global (row stride 256) through a double-buffered KTx256 SMEM tile.

__device__ __forceinline__ void zero_acc(float acc[8][8]) {
#pragma unroll
    for (int i = 0; i < 8; i++)
#pragma unroll
        for (int j = 0; j < 8; j++) acc[i][j] = 0.0f;
}

__device__ __forceinline__ void ldg_w(float4& v,
                                      const float* __restrict__ Wg,
                                      int k0, int kReal, int tid) {
    int r = tid >> 6;            // 0..3  (row within k-tile)
    int c = (tid & 63) << 2;     // 0..252 (4 floats per thread)
    int k = k0 + r;
    if (k < kReal) {
        v = *reinterpret_cast<const float4*>(Wg + (size_t)k * 256 + c);
    } else {
        v = make_float4(0.f, 0.f, 0.f, 0.f);
    }
}

__device__ __forceinline__ void sts_w(float* buf, float4 v, int tid) {
    int r = tid >> 6;
    int c = (tid & 63) << 2;
    *reinterpret_cast<float4*>(buf + r * 256 + c) = v;
}

// acc += src_s[0:kTiles*KT, 0:64]^T * W[0:kReal, 0:256]
// (padded src rows beyond real K must be zeroed by the caller; padded W rows load 0)
__device__ __forceinline__ void gemm_phase(float acc[8][8],
                                           const float* __restrict__ src_s, int kTiles,
                                           const float* __restrict__ Wg, int kReal,
                                           float* Ws, int tid, int tx, int ty) {
    __syncthreads();  // protect Ws buffers from any preceding phase's readers
    float4 pf;
    ldg_w(pf, Wg, 0, kReal, tid);
    for (int kt = 0; kt < kTiles; kt++) {
        float* buf = Ws + (kt & 1) * (KT * 256);
        sts_w(buf, pf, tid);
        if (kt + 1 < kTiles) ldg_w(pf, Wg, (kt + 1) * KT, kReal, tid);
        __syncthreads();
        const float* srck = src_s + kt * (KT * PCH);
#pragma unroll
        for (int k = 0; k < KT; k++) {
            float4 a0 = *reinterpret_cast<const float4*>(srck + k * PCH + ty * 8);
            float4 a1 = *reinterpret_cast<const float4*>(srck + k * PCH + ty * 8 + 4);
            float4 w0 = *reinterpret_cast<const float4*>(buf + k * 256 + tx * 4);
            float4 w1 = *reinterpret_cast<const float4*>(buf + k * 256 + tx * 4 + 128);
            float a[8] = {a0.x, a0.y, a0.z, a0.w, a1.x, a1.y, a1.z, a1.w};
            float w[8] = {w0.x, w0.y, w0.z, w0.w, w1.x, w1.y, w1.z, w1.w};
#pragma unroll
            for (int i = 0; i < 8; i++)
#pragma unroll
                for (int j = 0; j < 8; j++)
                    acc[i][j] = fmaf(a[i], w[j], acc[i][j]);
        }
        // no trailing sync needed: next iter writes the other buffer, and its
        // mid-iteration sync orders reuse two tiles later.
    }
}

// Write acc (+bias, optional relu) into dst k-major. Caller must sync before
// (all readers of dst done) and after (before anyone reads dst).
__device__ __forceinline__ void store_act(const float acc[8][8], float* dst,
                                          const float* bias_s, bool relu,
                                          int tx, int ty) {
#pragma unroll
    for (int j = 0; j < 8; j++) {
        int c = (j < 4) ? (tx * 4 + j) : (128 + tx * 4 + (j - 4));
        float b = bias_s[c];
#pragma unroll
        for (int i = 0; i < 8; i++) {
            float v = acc[i][j] + b;
            if (relu) v = fmaxf(v, 0.0f);
            dst[c * PCH + ty * 8 + i] = v;
        }
    }
}

// one full 256->256 relu layer (weights at Wg, bias at Bg), act_s in place
__device__ __forceinline__ void dense_layer_256(float acc[8][8], float* act_s,
                                                const float* __restrict__ Wg,
                                                const float* __restrict__ Bg,
                                                float* Ws, float* bias_s,
                                                int tid, int tx, int ty) {
    bias_s[tid] = Bg[tid];
    zero_acc(acc);
    gemm_phase(acc, act_s, 64, Wg, 256, Ws, tid, tx, ty);
    __syncthreads();
    store_act(acc, act_s, bias_s, true, tx, ty);
    __syncthreads();
}

// ---------------- gate kernel: 3 layers + LN + softmax + routing ----------------
// act_s ALIASES in_s: the 320-row input buffer is dead after layer 1's GEMM
// (all reads complete before the barrier preceding store_act).
__global__ __launch_bounds__(256, 2)
void gate_kernel(const float* __restrict__ x, const float* __restrict__ lat,
                 const float* __restrict__ gw1, const float* __restrict__ gb1,
                 const float* __restrict__ gw2, const float* __restrict__ gb2,
                 const float* __restrict__ lng, const float* __restrict__ lnb,
                 const float* __restrict__ gw3, const float* __restrict__ gb3) {
    extern __shared__ float sm[];
    float* in_s   = sm;                     // 320*PCH (row 319 zero pad)
    float* act_s  = in_s;                   // alias: reuses rows 0..255 after L1
    float* Ws     = in_s + 320 * PCH;       // 2*KT*256 (also layer-3 partial scratch)
    float* bias_s = Ws + 2 * KT * 256;      // 256
    float* w3_s   = bias_s + 256;           // 256*8
    float* mu_s   = w3_s + 2048;            // 64
    float* rs_s   = mu_s + 64;              // 64
    float* part_s = rs_s + 64;              // 4*64 partial sums

    int tid = threadIdx.x;
    int tx = tid & 31, ty = tid >> 5;
    int p0 = blockIdx.x * BM;

    // stage g_in = concat(x, shape_latent) transposed (k-major)
    for (int idx = tid; idx < 320 * BM; idx += 256) {
        int p = idx / 320;
        int k = idx - p * 320;
        int gp = p0 + p;
        float v;
        if (k < ENC)       v = x[(size_t)gp * ENC + k];
        else if (k < GIN)  v = lat[(size_t)gp * LAT + (k - ENC)];
        else               v = 0.0f;
        in_s[k * PCH + p] = v;
    }
    bias_s[tid] = gb1[tid];

    float acc[8][8];

    // layer 1: [319]->256, relu
    zero_acc(acc);
    gemm_phase(acc, in_s, 80, gw1, GIN, Ws, tid, tx, ty);
    __syncthreads();                 // all reads of in_s done -> safe to overwrite
    store_act(acc, act_s, bias_s, true, tx, ty);
    __syncthreads();

    // layer 2: 256->256, no relu
    bias_s[tid] = gb2[tid];
    zero_acc(acc);
    gemm_phase(acc, act_s, 64, gw2, 256, Ws, tid, tx, ty);
    __syncthreads();
    store_act(acc, act_s, bias_s, false, tx, ty);
    __syncthreads();

    // LayerNorm (two-pass, biased variance, eps 1e-5) — parallel reduction:
    // 256 threads compute 64-k partials (seg = tid>>6, p = tid&63), 64 combine.
    {
        int p = tid & 63, seg = tid >> 6;
        float s = 0.0f;
        for (int k = seg * 64; k < seg * 64 + 64; k++) s += act_s[k * PCH + p];
        part_s[seg * 64 + p] = s;
    }
    __syncthreads();
    if (tid < BM) {
        int p = tid;
        mu_s[p] = (part_s[p] + part_s[64 + p] + part_s[128 + p] + part_s[192 + p])
                  * (1.0f / 256.0f);
    }
    __syncthreads();
    {
        int p = tid & 63, seg = tid >> 6;
        float mu = mu_s[p];
        float v2 = 0.0f;
        for (int k = seg * 64; k < seg * 64 + 64; k++) {
            float d = act_s[k * PCH + p] - mu;
            v2 += d * d;
        }
        part_s[seg * 64 + p] = v2;
    }
    for (int idx = tid; idx < 2048; idx += 256) w3_s[idx] = gw3[idx];
    __syncthreads();
    if (tid < BM) {
        int p = tid;
        float v2 = part_s[p] + part_s[64 + p] + part_s[128 + p] + part_s[192 + p];
        rs_s[p] = rsqrtf(v2 * (1.0f / 256.0f) + 1e-5f);
    }
    __syncthreads();
    for (int idx = tid; idx < 256 * BM; idx += 256) {
        int k = idx >> 6, p = idx & 63;
        float v = act_s[k * PCH + p];
        act_s[k * PCH + p] = (v - mu_s[p]) * rs_s[p] * lng[k] + lnb[k];
    }
    __syncthreads();

    // layer 3: 256->8, parallel over 4 k-segments (partials in Ws — free here,
    // last gemm readers barriered off long before).
    {
        int p = tid & 63, seg = tid >> 6;
        float l[NE];
#pragma unroll
        for (int e = 0; e < NE; e++) l[e] = 0.0f;
        for (int k = seg * 64; k < seg * 64 + 64; k++) {
            float a = act_s[k * PCH + p];
#pragma unroll
            for (int e = 0; e < NE; e++) l[e] = fmaf(a, w3_s[k * 8 + e], l[e]);
        }
        float4* dst = reinterpret_cast<float4*>(Ws + seg * 512 + p * 8);
        dst[0] = make_float4(l[0], l[1], l[2], l[3]);
        dst[1] = make_float4(l[4], l[5], l[6], l[7]);
    }
    __syncthreads();

    // combine partials, softmax, argmax, routing (64 threads)
    if (tid < BM) {
        int p = tid;
        float l[NE];
#pragma unroll
        for (int e = 0; e < NE; e++) l[e] = gb3[e];
#pragma unroll
        for (int seg = 0; seg < 4; seg++) {
            const float4* src = reinterpret_cast<const float4*>(Ws + seg * 512 + p * 8);
            float4 a0 = src[0], a1 = src[1];
            l[0] += a0.x; l[1] += a0.y; l[2] += a0.z; l[3] += a0.w;
            l[4] += a1.x; l[5] += a1.y; l[6] += a1.z; l[7] += a1.w;
        }
        float m = l[0];
#pragma unroll
        for (int e = 1; e < NE; e++) m = fmaxf(m, l[e]);
        float g[NE], ssum = 0.0f;
#pragma unroll
        for (int e = 0; e < NE; e++) { g[e] = expf(l[e] - m); ssum += g[e]; }
        float inv = 1.0f / ssum;
#pragma unroll
        for (int e = 0; e < NE; e++) g[e] *= inv;
        // first-occurrence argmax over post-softmax gates (mirrors jnp.argmax)
        int bi = 0; float best = g[0];
#pragma unroll
        for (int e = 1; e < NE; e++) if (g[e] > best) { best = g[e]; bi = e; }
        int gp = p0 + p;
        d_gateval[gp] = best;
        int pos = atomicAdd(&d_counts[bi], 1);
        d_bucket[bi * B_PTS + pos] = gp;
    }
}

// ---------------- expert kernel: 7-layer NeRF MLP with skip at layer 5 ----------------
__global__ __launch_bounds__(256, 2)
void expert_kernel(const float* __restrict__ x, const float* __restrict__ lat,
                   const float* __restrict__ ew0, const float* __restrict__ eb0,
                   const float* __restrict__ ew1, const float* __restrict__ eb1,
                   const float* __restrict__ ew2, const float* __restrict__ eb2,
                   const float* __restrict__ ew3, const float* __restrict__ eb3,
                   const float* __restrict__ ew4, const float* __restrict__ eb4,
                   const float* __restrict__ ew5, const float* __restrict__ eb5,
                   const float* __restrict__ ew6, const float* __restrict__ eb6,
                   const float* __restrict__ ewo, const float* __restrict__ ebo,
                   float* __restrict__ out) {
    extern __shared__ float sm[];
    float* h0_s   = sm;                     // 96*PCH (row 95 zero pad)
    float* act_s  = h0_s + 96 * PCH;        // 256*PCH
    float* Ws     = act_s + 256 * PCH;      // 2*KT*256 (also head partial scratch)
    float* bias_s = Ws + 2 * KT * 256;      // 256
    float* wo_s   = bias_s + 256;           // 256*4
    int*   idx_s  = (int*)(wo_s + 1024);    // 64

    int e = blockIdx.y;
    int cnt = d_counts[e];
    int base = blockIdx.x * BM;
    if (base >= cnt) return;
    int nv = min(BM, cnt - base);

    int tid = threadIdx.x;
    int tx = tid & 31, ty = tid >> 5;

    if (tid < BM) {
        int slot = (tid < nv) ? tid : 0;   // clamp padding to a valid point
        idx_s[tid] = d_bucket[e * B_PTS + base + slot];
    }
    __syncthreads();

    // stage h0 = concat(x, latent chunk e) transposed (k-major)
    for (int idx = tid; idx < 96 * BM; idx += 256) {
        int k = idx >> 6, p = idx & 63;
        int gp = idx_s[p];
        float v;
        if (k < ENC)      v = x[(size_t)gp * ENC + k];
        else if (k < EIN) v = lat[(size_t)gp * LAT + e * CHUNK + (k - ENC)];
        else              v = 0.0f;
        h0_s[k * PCH + p] = v;
    }
    bias_s[tid] = eb0[e * 256 + tid];

    float acc[8][8];

    // layer 0: [95]->256, relu
    zero_acc(acc);
    gemm_phase(acc, h0_s, 24, ew0 + (size_t)e * EIN * 256, EIN, Ws, tid, tx, ty);
    __syncthreads();
    store_act(acc, act_s, bias_s, true, tx, ty);
    __syncthreads();

    // layers 1-4: 256->256, relu (fully unrolled: compile-time W/B pointers,
    // no local-memory pointer arrays)
    dense_layer_256(acc, act_s, ew1 + (size_t)e * 65536, eb1 + e * 256,
                    Ws, bias_s, tid, tx, ty);
    dense_layer_256(acc, act_s, ew2 + (size_t)e * 65536, eb2 + e * 256,
                    Ws, bias_s, tid, tx, ty);
    dense_layer_256(acc, act_s, ew3 + (size_t)e * 65536, eb3 + e * 256,
                    Ws, bias_s, tid, tx, ty);
    dense_layer_256(acc, act_s, ew4 + (size_t)e * 65536, eb4 + e * 256,
                    Ws, bias_s, tid, tx, ty);

    // layer 5 (skip): [act(256) ; h0(95)] -> 256, relu
    bias_s[tid] = eb5[e * 256 + tid];
    zero_acc(acc);
    gemm_phase(acc, act_s, 64, ew5 + (size_t)e * 351 * 256, 256, Ws, tid, tx, ty);
    gemm_phase(acc, h0_s, 24, ew5 + (size_t)e * 351 * 256 + 256 * 256, EIN, Ws, tid, tx, ty);
    __syncthreads();
    store_act(acc, act_s, bias_s, true, tx, ty);
    __syncthreads();

    // layer 6: 256->256, relu
    bias_s[tid] = eb6[e * 256 + tid];
    zero_acc(acc);
    gemm_phase(acc, act_s, 64, ew6 + (size_t)e * 65536, 256, Ws, tid, tx, ty);
    __syncthreads();
    store_act(acc, act_s, bias_s, true, tx, ty);

    // output head: 256->4, parallel over 4 k-segments (partials in Ws)
    for (int idx = tid; idx < 1024; idx += 256) wo_s[idx] = ewo[(size_t)e * 1024 + idx];
    __syncthreads();   // orders store_act writes + wo_s loads + frees Ws

    {
        int p = tid & 63, seg = tid >> 6;
        float o[NOUT] = {0.f, 0.f, 0.f, 0.f};
        for (int k = seg * 64; k < seg * 64 + 64; k++) {
            float a = act_s[k * PCH + p];
#pragma unroll
            for (int j = 0; j < NOUT; j++) o[j] = fmaf(a, wo_s[k * 4 + j], o[j]);
        }
        *reinterpret_cast<float4*>(Ws + seg * 256 + p * 4) =
            make_float4(o[0], o[1], o[2], o[3]);
    }
    __syncthreads();

    if (tid < nv) {
        int p = tid;
        float o[NOUT];
        float4 a0 = *reinterpret_cast<const float4*>(Ws + p * 4);
        float4 a1 = *reinterpret_cast<const float4*>(Ws + 256 + p * 4);
        float4 a2 = *reinterpret_cast<const float4*>(Ws + 512 + p * 4);
        float4 a3 = *reinterpret_cast<const float4*>(Ws + 768 + p * 4);
        o[0] = a0.x + a1.x + a2.x + a3.x;
        o[1] = a0.y + a1.y + a2.y + a3.y;
        o[2] = a0.z + a1.z + a2.z + a3.z;
        o[3] = a0.w + a1.w + a2.w + a3.w;
        int gp = idx_s[p];
        float gv = d_gateval[gp];
        float r[NOUT];
#pragma unroll
        for (int j = 0; j < NOUT; j++) {
            float y = o[j] + ebo[e * 4 + j];
            float c = gv * expf(y);
            if (c == 0.0f) c = EPS_F;
            r[j] = logf(c);
        }
        *reinterpret_cast<float4*>(out + (size_t)gp * 4) =
            make_float4(r[0], r[1], r[2], r[3]);
    }
}

// ---------------- launch ----------------
extern "C" void kernel_launch(void* const* d_in, const int* in_sizes, int n_in,
                              void* d_out, int out_size) {
    const float* x   = (const float*)d_in[0];
    const float* lat = (const float*)d_in[1];
    const float* gw1 = (const float*)d_in[2];
    const float* gb1 = (const float*)d_in[3];
    const float* gw2 = (const float*)d_in[4];
    const float* gb2 = (const float*)d_in[5];
    const float* lng = (const float*)d_in[6];
    const float* lnb = (const float*)d_in[7];
    const float* gw3 = (const float*)d_in[8];
    const float* gb3 = (const float*)d_in[9];
    const float* ew0 = (const float*)d_in[10];
    const float* eb0 = (const float*)d_in[11];
    const float* ew1 = (const float*)d_in[12];
    const float* eb1 = (const float*)d_in[13];
    const float* ew2 = (const float*)d_in[14];
    const float* eb2 = (const float*)d_in[15];
    const float* ew3 = (const float*)d_in[16];
    const float* eb3 = (const float*)d_in[17];
    const float* ew4 = (const float*)d_in[18];
    const float* eb4 = (const float*)d_in[19];
    const float* ew5 = (const float*)d_in[20];
    const float* eb5 = (const float*)d_in[21];
    const float* ew6 = (const float*)d_in[22];
    const float* eb6 = (const float*)d_in[23];
    const float* ewo = (const float*)d_in[24];
    const float* ebo = (const float*)d_in[25];
    float* out = (float*)d_out;

    const size_t gate_smem = (320 * PCH + 2 * KT * 256 + 256 + 2048 + 128 + 256)
                             * sizeof(float);
    const size_t exp_smem  = (96 * PCH + 256 * PCH + 2 * KT * 256 + 256 + 1024)
                             * sizeof(float) + 64 * sizeof(int);

    cudaFuncSetAttribute(gate_kernel,  cudaFuncAttributeMaxDynamicSharedMemorySize,
                         (int)gate_smem);
    cudaFuncSetAttribute(expert_kernel, cudaFuncAttributeMaxDynamicSharedMemorySize,
                         (int)exp_smem);

    zero_counts_kernel<<<1, 32>>>();
    gate_kernel<<<B_PTS / BM, 256, gate_smem>>>(x, lat, gw1, gb1, gw2, gb2,
                                                lng, lnb, gw3, gb3);
    dim3 eg(B_PTS / BM, NE);
    expert_kernel<<<eg, 256, exp_smem>>>(x, lat, ew0, eb0, ew1, eb1, ew2, eb2,
                                         ew3, eb3, ew4, eb4, ew5, eb5, ew6, eb6,
                                         ewo, ebo, out);
}